// round 1
// baseline (speedup 1.0000x reference)
#include <cuda_runtime.h>
#include <math.h>

#define B_    4
#define LQ_   4096
#define LKV_  256
#define D_    1024
#define H_    16
#define KVH_  4
#define HD_   64

// Scratch: device globals (no allocation allowed anywhere).
__device__ float g_Q[(size_t)B_ * LQ_ * D_];            // 64 MB
__device__ float g_K[(size_t)B_ * LKV_ * KVH_ * HD_];   // 1 MB
__device__ float g_V[(size_t)B_ * LKV_ * KVH_ * HD_];   // 1 MB
__device__ float g_attn[(size_t)B_ * LQ_ * D_];         // 64 MB

// ---------------------------------------------------------------------------
// SGEMM: C[M,N] = A[M,K] @ W[K,N] + bias[N]   (all row-major, fp32)
// 128x128 block tile, BK=8, 8x8 per-thread microtile, 256 threads.
// Requires M%128==0, N%128==0, K%8==0 (true for all shapes here).
// ---------------------------------------------------------------------------
__global__ __launch_bounds__(256)
void sgemm_bias(const float* __restrict__ A, const float* __restrict__ W,
                const float* __restrict__ bias, float* __restrict__ C,
                int M, int N, int K)
{
    const int BM = 128, BN = 128, BK = 8, TM = 8, TN = 8;
    __shared__ float As[BK][BM];
    __shared__ float Bs[BK][BN];

    int tid = threadIdx.x;
    int bm = blockIdx.y, bn = blockIdx.x;

    int aRow = tid >> 1;            // 0..127
    int aCol = (tid & 1) << 2;      // 0 or 4
    int bRow = tid >> 5;            // 0..7
    int bCol = (tid & 31) << 2;     // 0..124 step 4
    int tRow = (tid >> 4) << 3;     // 0..120 step 8
    int tCol = (tid & 15) << 3;     // 0..120 step 8

    const float* Ap = A + (size_t)bm * BM * K;
    const float* Bp = W + bn * BN;

    float acc[TM][TN];
#pragma unroll
    for (int i = 0; i < TM; i++)
#pragma unroll
        for (int j = 0; j < TN; j++) acc[i][j] = 0.f;

    for (int k0 = 0; k0 < K; k0 += BK) {
        float4 av = *reinterpret_cast<const float4*>(Ap + (size_t)aRow * K + k0 + aCol);
        As[aCol + 0][aRow] = av.x;
        As[aCol + 1][aRow] = av.y;
        As[aCol + 2][aRow] = av.z;
        As[aCol + 3][aRow] = av.w;
        *reinterpret_cast<float4*>(&Bs[bRow][bCol]) =
            *reinterpret_cast<const float4*>(Bp + (size_t)(k0 + bRow) * N + bCol);
        __syncthreads();

#pragma unroll
        for (int kk = 0; kk < BK; kk++) {
            float ar[TM], br[TN];
#pragma unroll
            for (int i = 0; i < TM; i++) ar[i] = As[kk][tRow + i];
#pragma unroll
            for (int j = 0; j < TN; j++) br[j] = Bs[kk][tCol + j];
#pragma unroll
            for (int i = 0; i < TM; i++)
#pragma unroll
                for (int j = 0; j < TN; j++)
                    acc[i][j] += ar[i] * br[j];
        }
        __syncthreads();
    }

#pragma unroll
    for (int i = 0; i < TM; i++) {
#pragma unroll
        for (int j = 0; j < TN; j += 4) {
            int col = bn * BN + tCol + j;
            float4 o;
            o.x = acc[i][j + 0] + bias[col + 0];
            o.y = acc[i][j + 1] + bias[col + 1];
            o.z = acc[i][j + 2] + bias[col + 2];
            o.w = acc[i][j + 3] + bias[col + 3];
            *reinterpret_cast<float4*>(C + (size_t)(bm * BM + tRow + i) * N + col) = o;
        }
    }
}

// ---------------------------------------------------------------------------
// RoPE in-place on X of shape (B_, L, Hn, 64). One thread per (b,l,h,j<32).
// pos = l / (L / nf).  inv_freq = 10000^(-2j/64).
// ---------------------------------------------------------------------------
__global__ void rope_kernel(float* __restrict__ X, int L, int Hn,
                            const int* __restrict__ nf_ptr, int total)
{
    int nf = *nf_ptr;
    if (nf <= 1) return;
    int idx = blockIdx.x * blockDim.x + threadIdx.x;
    if (idx >= total) return;

    int j   = idx & 31;
    int h   = (idx >> 5) % Hn;
    int rem = idx / (32 * Hn);
    int l   = rem % L;
    int b   = rem / L;

    int pos = l / (L / nf);
    float inv_freq = powf(10000.0f, -(float)(2 * j) / 64.0f);
    float th = (float)pos * inv_freq;
    float c = cosf(th), s = sinf(th);

    float* p = X + (size_t)((b * L + l) * Hn + h) * HD_;
    float x1 = p[j], x2 = p[j + 32];
    p[j]      = x1 * c - x2 * s;
    p[j + 32] = x2 * c + x1 * s;
}

// ---------------------------------------------------------------------------
// Attention: grid (LQ/256, H, B), 256 threads. K/V for the kv-head staged in
// dynamic SMEM (2 * 256*64 fp32 = 128 KB). Each thread owns one query row.
// Softmax without max-subtraction (scores ~N(0,1); exp safe).
// ---------------------------------------------------------------------------
__global__ __launch_bounds__(256)
void attn_kernel(const float* __restrict__ Q, const float* __restrict__ Kg,
                 const float* __restrict__ Vg, float* __restrict__ O)
{
    extern __shared__ float sh[];
    float* Ks = sh;                 // [256][64]
    float* Vs = sh + LKV_ * HD_;    // [256][64]

    int b = blockIdx.z, h = blockIdx.y;
    int kvh = h / (H_ / KVH_);
    int tid = threadIdx.x;

    // Cooperative K/V load (float4). Row stride in gmem = KVH_*HD_.
    for (int i = tid; i < LKV_ * HD_ / 4; i += 256) {
        int l  = i >> 4;        // (i*4)/64
        int d  = (i & 15) << 2; // (i*4)%64
        size_t off = ((size_t)(b * LKV_ + l) * KVH_ + kvh) * HD_ + d;
        reinterpret_cast<float4*>(Ks)[i] = *reinterpret_cast<const float4*>(Kg + off);
        reinterpret_cast<float4*>(Vs)[i] = *reinterpret_cast<const float4*>(Vg + off);
    }
    __syncthreads();

    int qr = blockIdx.x * 256 + tid;
    const float* qp = Q + ((size_t)b * LQ_ + qr) * D_ + h * HD_;

    float q[HD_];
#pragma unroll
    for (int d4 = 0; d4 < 16; d4++) {
        float4 v = reinterpret_cast<const float4*>(qp)[d4];
        q[4 * d4 + 0] = v.x * 0.125f;   // fold in 1/sqrt(64)
        q[4 * d4 + 1] = v.y * 0.125f;
        q[4 * d4 + 2] = v.z * 0.125f;
        q[4 * d4 + 3] = v.w * 0.125f;
    }

    float acc[HD_];
#pragma unroll
    for (int d = 0; d < HD_; d++) acc[d] = 0.f;
    float lsum = 0.f;

    for (int k = 0; k < LKV_; k++) {
        const float* kr = Ks + k * HD_;
        float s0 = 0.f, s1 = 0.f, s2 = 0.f, s3 = 0.f;
#pragma unroll
        for (int d = 0; d < HD_; d += 4) {
            s0 += q[d + 0] * kr[d + 0];
            s1 += q[d + 1] * kr[d + 1];
            s2 += q[d + 2] * kr[d + 2];
            s3 += q[d + 3] * kr[d + 3];
        }
        float p = expf((s0 + s1) + (s2 + s3));
        lsum += p;
        const float* vr = Vs + k * HD_;
#pragma unroll
        for (int d = 0; d < HD_; d++) acc[d] += p * vr[d];
    }

    float inv = 1.0f / lsum;
    float* op = O + ((size_t)b * LQ_ + qr) * D_ + h * HD_;
#pragma unroll
    for (int d4 = 0; d4 < 16; d4++) {
        float4 o;
        o.x = acc[4 * d4 + 0] * inv;
        o.y = acc[4 * d4 + 1] * inv;
        o.z = acc[4 * d4 + 2] * inv;
        o.w = acc[4 * d4 + 3] * inv;
        reinterpret_cast<float4*>(op)[d4] = o;
    }
}

// ---------------------------------------------------------------------------
extern "C" void kernel_launch(void* const* d_in, const int* in_sizes, int n_in,
                              void* d_out, int out_size)
{
    const float* patches = (const float*)d_in[0];
    const float* latents = (const float*)d_in[1];
    const float* Wq = (const float*)d_in[2];
    const float* bq = (const float*)d_in[3];
    const float* Wk = (const float*)d_in[4];
    const float* bk = (const float*)d_in[5];
    const float* Wv = (const float*)d_in[6];
    const float* bv = (const float*)d_in[7];
    const float* Wo = (const float*)d_in[8];
    const float* bo = (const float*)d_in[9];
    const int*   nf = (const int*)d_in[10];
    float* out = (float*)d_out;

    float *Qd, *Kd, *Vd, *Ad;
    cudaGetSymbolAddress((void**)&Qd, g_Q);
    cudaGetSymbolAddress((void**)&Kd, g_K);
    cudaGetSymbolAddress((void**)&Vd, g_V);
    cudaGetSymbolAddress((void**)&Ad, g_attn);

    // Allow 128 KB dynamic smem for attention (idempotent host-side call).
    cudaFuncSetAttribute(attn_kernel, cudaFuncAttributeMaxDynamicSharedMemorySize,
                         2 * LKV_ * HD_ * (int)sizeof(float));

    // 1) Q projection: (B*LQ, D) @ (D, D) + bq
    dim3 gq(D_ / 128, (B_ * LQ_) / 128);
    sgemm_bias<<<gq, 256>>>(patches, Wq, bq, Qd, B_ * LQ_, D_, D_);

    // 2) K / V projections: (B*LKV, D) @ (D, KVH*HD) + bias
    dim3 gkv((KVH_ * HD_) / 128, (B_ * LKV_) / 128);
    sgemm_bias<<<gkv, 256>>>(latents, Wk, bk, Kd, B_ * LKV_, KVH_ * HD_, D_);
    sgemm_bias<<<gkv, 256>>>(latents, Wv, bv, Vd, B_ * LKV_, KVH_ * HD_, D_);

    // 3) RoPE on Q and K
    int nq = B_ * LQ_ * H_ * (HD_ / 2);
    rope_kernel<<<(nq + 255) / 256, 256>>>(Qd, LQ_, H_, nf, nq);
    int nk = B_ * LKV_ * KVH_ * (HD_ / 2);
    rope_kernel<<<(nk + 255) / 256, 256>>>(Kd, LKV_, KVH_, nf, nk);

    // 4) Attention -> g_attn
    dim3 ga(LQ_ / 256, H_, B_);
    attn_kernel<<<ga, 256, 2 * LKV_ * HD_ * (int)sizeof(float)>>>(Qd, Kd, Vd, Ad);

    // 5) Output projection: (B*LQ, D) @ (D, D) + bo -> out
    sgemm_bias<<<gq, 256>>>(Ad, Wo, bo, out, B_ * LQ_, D_, D_);
}

// round 3
// speedup vs baseline: 2.4360x; 2.4360x over previous
#include <cuda_runtime.h>
#include <math.h>
#include <stdint.h>

#define B_    4
#define LQ_   4096
#define LKV_  256
#define D_    1024
#define H_    16
#define KVH_  4
#define HD_   64
#define NF_MAX 4096

// ---------------- scratch (device globals; no allocation allowed) ----------
__device__ float g_P[(size_t)B_ * LQ_ * D_];            // tf32-rounded patches
__device__ float g_L[(size_t)B_ * LKV_ * D_];           // tf32-rounded latents
__device__ float g_Q[(size_t)B_ * LQ_ * D_];
__device__ float g_K[(size_t)B_ * LKV_ * KVH_ * HD_];
__device__ float g_V[(size_t)B_ * LKV_ * KVH_ * HD_];
__device__ float g_attn[(size_t)B_ * LQ_ * D_];         // tf32-rounded attn out
__device__ float g_WtQ[(size_t)D_ * D_];                // W^T [N][K], tf32-rounded
__device__ float g_WtK[(size_t)(KVH_ * HD_) * D_];
__device__ float g_WtV[(size_t)(KVH_ * HD_) * D_];
__device__ float g_WtO[(size_t)D_ * D_];
__device__ float g_rope[2 * NF_MAX * 32];               // cos | sin

// ---------------- helpers ---------------------------------------------------
__device__ __forceinline__ uint32_t smem_u32(const void* p) {
    uint32_t a;
    asm("{ .reg .u64 t; cvta.to.shared.u64 t, %1; cvt.u32.u64 %0, t; }"
        : "=r"(a) : "l"(p));
    return a;
}
__device__ __forceinline__ uint32_t sw128(uint32_t off) {
    return off ^ ((off >> 3) & 0x70);
}
__device__ __forceinline__ float to_tf32(float x) {
    uint32_t u;
    asm("cvt.rna.tf32.f32 %0, %1;" : "=r"(u) : "f"(x));
    return __uint_as_float(u);
}

#define CP_A16(d, s) \
    asm volatile("cp.async.cg.shared.global [%0], [%1], 16;" :: "r"(d), "l"(s) : "memory")
#define CP_COMMIT() asm volatile("cp.async.commit_group;" ::: "memory")
#define CP_WAIT1()  asm volatile("cp.async.wait_group 1;" ::: "memory")
#define CP_WAIT0()  asm volatile("cp.async.wait_group 0;" ::: "memory")
#define LDSM4(r, addr) \
    asm volatile("ldmatrix.sync.aligned.m8n8.x4.shared.b16 {%0,%1,%2,%3}, [%4];" \
        : "=r"((r)[0]), "=r"((r)[1]), "=r"((r)[2]), "=r"((r)[3]) : "r"(addr))
#define MMA_TF32(d, a0, a1, a2, a3, b0, b1) \
    asm volatile("mma.sync.aligned.m16n8k8.row.col.f32.tf32.tf32.f32 " \
        "{%0,%1,%2,%3}, {%4,%5,%6,%7}, {%8,%9}, {%0,%1,%2,%3};" \
        : "+f"((d)[0]), "+f"((d)[1]), "+f"((d)[2]), "+f"((d)[3]) \
        : "r"(a0), "r"(a1), "r"(a2), "r"(a3), "r"(b0), "r"(b1))

// ---------------------------------------------------------------------------
// tf32 round: out[i] = round_tf32(in[i]), vectorized
// ---------------------------------------------------------------------------
__global__ void cvt_tf32_kernel(const float* __restrict__ in, float* __restrict__ out, int n4)
{
    int i = blockIdx.x * blockDim.x + threadIdx.x;
    if (i >= n4) return;
    float4 v = reinterpret_cast<const float4*>(in)[i];
    v.x = to_tf32(v.x); v.y = to_tf32(v.y);
    v.z = to_tf32(v.z); v.w = to_tf32(v.w);
    reinterpret_cast<float4*>(out)[i] = v;
}

// ---------------------------------------------------------------------------
// Weight transpose + tf32 round: Wt[n*K + k] = tf32(W[k*N + n])
// ---------------------------------------------------------------------------
__global__ void transpose_kernel(const float* __restrict__ W, float* __restrict__ Wt,
                                 int K, int N)
{
    __shared__ float t[32][33];
    int nb = blockIdx.x * 32, kb = blockIdx.y * 32;
    int x = threadIdx.x, y = threadIdx.y;   // 32 x 8
#pragma unroll
    for (int i = 0; i < 32; i += 8)
        t[y + i][x] = W[(size_t)(kb + y + i) * N + nb + x];
    __syncthreads();
#pragma unroll
    for (int i = 0; i < 32; i += 8)
        Wt[(size_t)(nb + y + i) * K + kb + x] = to_tf32(t[x][y + i]);
}

// ---------------------------------------------------------------------------
// RoPE cos/sin table
// ---------------------------------------------------------------------------
__global__ void rope_table_kernel(const int* __restrict__ nf_ptr)
{
    int nf = *nf_ptr;
    if (nf <= 1 || nf > NF_MAX) return;
    int idx = blockIdx.x * blockDim.x + threadIdx.x;
    if (idx >= nf * 32) return;
    int j = idx & 31, pos = idx >> 5;
    float inv = powf(10000.0f, -(float)(2 * j) / 64.0f);
    float th = (float)pos * inv;
    g_rope[idx] = cosf(th);
    g_rope[NF_MAX * 32 + idx] = sinf(th);
}

// ---------------------------------------------------------------------------
// tf32 mma.sync GEMM: C[M,N] = A[M,K] @ Bt[N,K]^T + bias
// 128x128x32 tile, 256 threads (8 warps, warp tile 64x32), cp.async dbl-buffer.
// Inputs A, Bt must already be tf32-rounded.
// ---------------------------------------------------------------------------
__device__ __forceinline__ void load_tile(const float* Ag, const float* Bg, int K,
                                          uint32_t aBuf, uint32_t bBuf, int tid)
{
#pragma unroll
    for (int j = 0; j < 4; j++) {
        int idx = j * 256 + tid;
        int row = idx >> 3, k4 = idx & 7;
        uint32_t off = sw128((uint32_t)(row * 128 + k4 * 16));
        CP_A16(aBuf + off, Ag + (size_t)row * K + k4 * 4);
        CP_A16(bBuf + off, Bg + (size_t)row * K + k4 * 4);
    }
}

__global__ __launch_bounds__(256)
void gemm_tf32(const float* __restrict__ A, const float* __restrict__ Bt,
               const float* __restrict__ bias, float* __restrict__ C,
               int M, int N, int K)
{
    extern __shared__ char smraw[];
    uint32_t base = smem_u32(smraw);
    uint32_t data = (base + 1023u) & ~1023u;

    int tid = threadIdx.x, lane = tid & 31, wid = tid >> 5;
    int wm = (wid >> 2) * 64;   // 2 warp-rows
    int wn = (wid & 3) * 32;    // 4 warp-cols

    const float* Ag = A  + (size_t)blockIdx.y * 128 * K;
    const float* Bg = Bt + (size_t)blockIdx.x * 128 * K;

    float acc[4][4][4];
#pragma unroll
    for (int i = 0; i < 4; i++)
#pragma unroll
        for (int j = 0; j < 4; j++)
#pragma unroll
            for (int k = 0; k < 4; k++) acc[i][j][k] = 0.f;

    int T = K >> 5;
    load_tile(Ag, Bg, K, data, data + 16384u, tid);
    CP_COMMIT();

    int lmat = lane >> 3, lrow = lane & 7;
    int frow = ((lmat & 2) ? 8 : 0) + lrow;   // ldmatrix source row within 16-block
    int fcol = (lmat & 1) * 16;               // 16B half within k-step

    for (int t = 0; t < T; ++t) {
        int st = t & 1;
        if (t + 1 < T) {
            uint32_t nb = data + (uint32_t)((t + 1) & 1) * 32768u;
            load_tile(Ag + (t + 1) * 32, Bg + (t + 1) * 32, K, nb, nb + 16384u, tid);
            CP_COMMIT();
            CP_WAIT1();
        } else {
            CP_WAIT0();
        }
        __syncthreads();

        uint32_t aB = data + (uint32_t)st * 32768u;
        uint32_t bB = aB + 16384u;
#pragma unroll
        for (int kk = 0; kk < 4; ++kk) {
            uint32_t af[4][4], bf[2][4];
#pragma unroll
            for (int mi = 0; mi < 4; ++mi) {
                uint32_t addr = aB + sw128((uint32_t)((wm + mi * 16 + frow) * 128 + kk * 32 + fcol));
                LDSM4(af[mi], addr);
            }
#pragma unroll
            for (int nj = 0; nj < 2; ++nj) {
                uint32_t addr = bB + sw128((uint32_t)((wn + nj * 16 + frow) * 128 + kk * 32 + fcol));
                LDSM4(bf[nj], addr);
            }
#pragma unroll
            for (int mi = 0; mi < 4; ++mi)
#pragma unroll
                for (int ni = 0; ni < 4; ++ni) {
                    int nj = ni >> 1, lh = (ni & 1) * 2;
                    MMA_TF32(acc[mi][ni],
                             af[mi][0], af[mi][2], af[mi][1], af[mi][3],
                             bf[nj][lh], bf[nj][lh + 1]);
                }
        }
        __syncthreads();
    }

    // Epilogue: c0,c1 -> (row, col*2..+1); c2,c3 -> row+8
    int rbase = blockIdx.y * 128 + wm + (lane >> 2);
    int cbase = blockIdx.x * 128 + wn + (lane & 3) * 2;
#pragma unroll
    for (int mi = 0; mi < 4; ++mi) {
#pragma unroll
        for (int ni = 0; ni < 4; ++ni) {
            int c = cbase + ni * 8;
            float2 bv = *(const float2*)(bias + c);
            int r0 = rbase + mi * 16;
            float2 v0 = { acc[mi][ni][0] + bv.x, acc[mi][ni][1] + bv.y };
            *(float2*)(C + (size_t)r0 * N + c) = v0;
            float2 v1 = { acc[mi][ni][2] + bv.x, acc[mi][ni][3] + bv.y };
            *(float2*)(C + (size_t)(r0 + 8) * N + c) = v1;
        }
    }
}

// ---------------------------------------------------------------------------
// Attention with fused RoPE. grid (LQ/256, H, B), 256 threads.
// Output is tf32-rounded (feeds the O-projection GEMM).
// ---------------------------------------------------------------------------
__global__ __launch_bounds__(256)
void attn_kernel(const float* __restrict__ Q, const float* __restrict__ Kg,
                 const float* __restrict__ Vg, float* __restrict__ O,
                 const int* __restrict__ nf_ptr)
{
    extern __shared__ float sh[];
    float* Ks = sh;                 // [256][64]
    float* Vs = sh + LKV_ * HD_;    // [256][64]

    int b = blockIdx.z, h = blockIdx.y;
    int kvh = h / (H_ / KVH_);
    int tid = threadIdx.x;
    int nf = *nf_ptr;

    for (int i = tid; i < LKV_ * HD_ / 4; i += 256) {
        int l = i >> 4;
        int d = (i & 15) << 2;
        size_t off = ((size_t)(b * LKV_ + l) * KVH_ + kvh) * HD_ + d;
        reinterpret_cast<float4*>(Ks)[i] = *reinterpret_cast<const float4*>(Kg + off);
        reinterpret_cast<float4*>(Vs)[i] = *reinterpret_cast<const float4*>(Vg + off);
    }
    __syncthreads();

    if (nf > 1) {
        int kdiv = LKV_ / nf;
        for (int i = tid; i < LKV_ * 32; i += 256) {
            int l = i >> 5, j = i & 31;
            int pos = l / kdiv;
            float c = g_rope[pos * 32 + j];
            float s = g_rope[NF_MAX * 32 + pos * 32 + j];
            float x1 = Ks[l * 64 + j], x2 = Ks[l * 64 + j + 32];
            Ks[l * 64 + j]      = x1 * c - x2 * s;
            Ks[l * 64 + j + 32] = x2 * c + x1 * s;
        }
        __syncthreads();
    }

    int qr = blockIdx.x * 256 + tid;
    const float* qp = Q + ((size_t)b * LQ_ + qr) * D_ + h * HD_;

    float q[HD_];
#pragma unroll
    for (int d4 = 0; d4 < 16; d4++) {
        float4 v = reinterpret_cast<const float4*>(qp)[d4];
        q[4 * d4 + 0] = v.x * 0.125f;
        q[4 * d4 + 1] = v.y * 0.125f;
        q[4 * d4 + 2] = v.z * 0.125f;
        q[4 * d4 + 3] = v.w * 0.125f;
    }
    if (nf > 1) {
        int pos = qr / (LQ_ / nf);
        const float* ct = g_rope + pos * 32;
        const float* st = g_rope + NF_MAX * 32 + pos * 32;
#pragma unroll
        for (int j = 0; j < 32; j++) {
            float c = ct[j], s = st[j];
            float x1 = q[j], x2 = q[j + 32];
            q[j]      = x1 * c - x2 * s;
            q[j + 32] = x2 * c + x1 * s;
        }
    }

    float acc[HD_];
#pragma unroll
    for (int d = 0; d < HD_; d++) acc[d] = 0.f;
    float lsum = 0.f;

    for (int k = 0; k < LKV_; k++) {
        const float* kr = Ks + k * HD_;
        float s0 = 0.f, s1 = 0.f, s2 = 0.f, s3 = 0.f;
#pragma unroll
        for (int d = 0; d < HD_; d += 4) {
            s0 += q[d + 0] * kr[d + 0];
            s1 += q[d + 1] * kr[d + 1];
            s2 += q[d + 2] * kr[d + 2];
            s3 += q[d + 3] * kr[d + 3];
        }
        float p = __expf((s0 + s1) + (s2 + s3));
        lsum += p;
        const float* vr = Vs + k * HD_;
#pragma unroll
        for (int d = 0; d < HD_; d++) acc[d] += p * vr[d];
    }

    float inv = 1.0f / lsum;
    float* op = O + ((size_t)b * LQ_ + qr) * D_ + h * HD_;
#pragma unroll
    for (int d4 = 0; d4 < 16; d4++) {
        float4 o;
        o.x = to_tf32(acc[4 * d4 + 0] * inv);
        o.y = to_tf32(acc[4 * d4 + 1] * inv);
        o.z = to_tf32(acc[4 * d4 + 2] * inv);
        o.w = to_tf32(acc[4 * d4 + 3] * inv);
        reinterpret_cast<float4*>(op)[d4] = o;
    }
}

// ---------------------------------------------------------------------------
extern "C" void kernel_launch(void* const* d_in, const int* in_sizes, int n_in,
                              void* d_out, int out_size)
{
    const float* patches = (const float*)d_in[0];
    const float* latents = (const float*)d_in[1];
    const float* Wq = (const float*)d_in[2];
    const float* bq = (const float*)d_in[3];
    const float* Wk = (const float*)d_in[4];
    const float* bk = (const float*)d_in[5];
    const float* Wv = (const float*)d_in[6];
    const float* bv = (const float*)d_in[7];
    const float* Wo = (const float*)d_in[8];
    const float* bo = (const float*)d_in[9];
    const int*   nf = (const int*)d_in[10];
    float* out = (float*)d_out;

    float *Pd, *Ld, *Qd, *Kd, *Vd, *Ad, *WtQ, *WtK, *WtV, *WtO;
    cudaGetSymbolAddress((void**)&Pd,  g_P);
    cudaGetSymbolAddress((void**)&Ld,  g_L);
    cudaGetSymbolAddress((void**)&Qd,  g_Q);
    cudaGetSymbolAddress((void**)&Kd,  g_K);
    cudaGetSymbolAddress((void**)&Vd,  g_V);
    cudaGetSymbolAddress((void**)&Ad,  g_attn);
    cudaGetSymbolAddress((void**)&WtQ, g_WtQ);
    cudaGetSymbolAddress((void**)&WtK, g_WtK);
    cudaGetSymbolAddress((void**)&WtV, g_WtV);
    cudaGetSymbolAddress((void**)&WtO, g_WtO);

    const int GEMM_SMEM = 1024 + 4 * 16384;
    cudaFuncSetAttribute(gemm_tf32, cudaFuncAttributeMaxDynamicSharedMemorySize, GEMM_SMEM);
    cudaFuncSetAttribute(attn_kernel, cudaFuncAttributeMaxDynamicSharedMemorySize,
                         2 * LKV_ * HD_ * (int)sizeof(float));

    // 0) prep: transposed tf32 weights, tf32 activations, RoPE table
    dim3 tb(32, 8);
    transpose_kernel<<<dim3(D_ / 32, D_ / 32), tb>>>(Wq, WtQ, D_, D_);
    transpose_kernel<<<dim3((KVH_ * HD_) / 32, D_ / 32), tb>>>(Wk, WtK, D_, KVH_ * HD_);
    transpose_kernel<<<dim3((KVH_ * HD_) / 32, D_ / 32), tb>>>(Wv, WtV, D_, KVH_ * HD_);
    transpose_kernel<<<dim3(D_ / 32, D_ / 32), tb>>>(Wo, WtO, D_, D_);
    rope_table_kernel<<<(NF_MAX * 32) / 256, 256>>>(nf);
    int np4 = B_ * LQ_ * D_ / 4;
    cvt_tf32_kernel<<<(np4 + 255) / 256, 256>>>(patches, Pd, np4);
    int nl4 = B_ * LKV_ * D_ / 4;
    cvt_tf32_kernel<<<(nl4 + 255) / 256, 256>>>(latents, Ld, nl4);

    // 1) Q projection
    gemm_tf32<<<dim3(D_ / 128, (B_ * LQ_) / 128), 256, GEMM_SMEM>>>(
        Pd, WtQ, bq, Qd, B_ * LQ_, D_, D_);

    // 2) K / V projections
    gemm_tf32<<<dim3((KVH_ * HD_) / 128, (B_ * LKV_) / 128), 256, GEMM_SMEM>>>(
        Ld, WtK, bk, Kd, B_ * LKV_, KVH_ * HD_, D_);
    gemm_tf32<<<dim3((KVH_ * HD_) / 128, (B_ * LKV_) / 128), 256, GEMM_SMEM>>>(
        Ld, WtV, bv, Vd, B_ * LKV_, KVH_ * HD_, D_);

    // 3) attention (RoPE fused) -> tf32-rounded g_attn
    dim3 ga(LQ_ / 256, H_, B_);
    attn_kernel<<<ga, 256, 2 * LKV_ * HD_ * (int)sizeof(float)>>>(Qd, Kd, Vd, Ad, nf);

    // 4) output projection
    gemm_tf32<<<dim3(D_ / 128, (B_ * LQ_) / 128), 256, GEMM_SMEM>>>(
        Ad, WtO, bo, out, B_ * LQ_, D_, D_);
}

// round 4
// speedup vs baseline: 3.8986x; 1.6004x over previous
#include <cuda_runtime.h>
#include <math.h>
#include <stdint.h>

#define B_    4
#define LQ_   4096
#define LKV_  256
#define D_    1024
#define H_    16
#define KVH_  4
#define HD_   64
#define NF_MAX 4096

// ---------------- scratch (device globals; no allocation allowed) ----------
__device__ float g_P[(size_t)B_ * LQ_ * D_];            // tf32-rounded patches
__device__ float g_L[(size_t)B_ * LKV_ * D_];           // tf32-rounded latents
__device__ float g_Q[(size_t)B_ * LQ_ * D_];
__device__ float g_K[(size_t)B_ * LKV_ * KVH_ * HD_];
__device__ float g_V[(size_t)B_ * LKV_ * KVH_ * HD_];
__device__ float g_attn[(size_t)B_ * LQ_ * D_];         // tf32-rounded attn out
__device__ float g_WtQ[(size_t)D_ * D_];                // W^T [N][K], tf32-rounded
__device__ float g_WtK[(size_t)(KVH_ * HD_) * D_];
__device__ float g_WtV[(size_t)(KVH_ * HD_) * D_];
__device__ float g_WtO[(size_t)D_ * D_];
__device__ float g_rope[2 * NF_MAX * 32];               // cos | sin

// ---------------- helpers ---------------------------------------------------
__device__ __forceinline__ uint32_t smem_u32(const void* p) {
    uint32_t a;
    asm("{ .reg .u64 t; cvta.to.shared.u64 t, %1; cvt.u32.u64 %0, t; }"
        : "=r"(a) : "l"(p));
    return a;
}
__device__ __forceinline__ uint32_t sw128(uint32_t off) {
    return off ^ ((off >> 3) & 0x70);
}
__device__ __forceinline__ float to_tf32(float x) {
    uint32_t u;
    asm("cvt.rna.tf32.f32 %0, %1;" : "=r"(u) : "f"(x));
    return __uint_as_float(u);
}

#define CP_A16(d, s) \
    asm volatile("cp.async.cg.shared.global [%0], [%1], 16;" :: "r"(d), "l"(s) : "memory")
#define CP_COMMIT() asm volatile("cp.async.commit_group;" ::: "memory")
#define CP_WAIT1()  asm volatile("cp.async.wait_group 1;" ::: "memory")
#define CP_WAIT0()  asm volatile("cp.async.wait_group 0;" ::: "memory")
#define LDSM4(r, addr) \
    asm volatile("ldmatrix.sync.aligned.m8n8.x4.shared.b16 {%0,%1,%2,%3}, [%4];" \
        : "=r"((r)[0]), "=r"((r)[1]), "=r"((r)[2]), "=r"((r)[3]) : "r"(addr))
#define MMA_TF32(d, a0, a1, a2, a3, b0, b1) \
    asm volatile("mma.sync.aligned.m16n8k8.row.col.f32.tf32.tf32.f32 " \
        "{%0,%1,%2,%3}, {%4,%5,%6,%7}, {%8,%9}, {%0,%1,%2,%3};" \
        : "+f"((d)[0]), "+f"((d)[1]), "+f"((d)[2]), "+f"((d)[3]) \
        : "r"(a0), "r"(a1), "r"(a2), "r"(a3), "r"(b0), "r"(b1))

// ---------------------------------------------------------------------------
__global__ void cvt_tf32_kernel(const float* __restrict__ in, float* __restrict__ out, int n4)
{
    int i = blockIdx.x * blockDim.x + threadIdx.x;
    if (i >= n4) return;
    float4 v = reinterpret_cast<const float4*>(in)[i];
    v.x = to_tf32(v.x); v.y = to_tf32(v.y);
    v.z = to_tf32(v.z); v.w = to_tf32(v.w);
    reinterpret_cast<float4*>(out)[i] = v;
}

__global__ void transpose_kernel(const float* __restrict__ W, float* __restrict__ Wt,
                                 int K, int N)
{
    __shared__ float t[32][33];
    int nb = blockIdx.x * 32, kb = blockIdx.y * 32;
    int x = threadIdx.x, y = threadIdx.y;   // 32 x 8
#pragma unroll
    for (int i = 0; i < 32; i += 8)
        t[y + i][x] = W[(size_t)(kb + y + i) * N + nb + x];
    __syncthreads();
#pragma unroll
    for (int i = 0; i < 32; i += 8)
        Wt[(size_t)(nb + y + i) * K + kb + x] = to_tf32(t[x][y + i]);
}

__global__ void rope_table_kernel(const int* __restrict__ nf_ptr)
{
    int nf = *nf_ptr;
    if (nf <= 1 || nf > NF_MAX) return;
    int idx = blockIdx.x * blockDim.x + threadIdx.x;
    if (idx >= nf * 32) return;
    int j = idx & 31, pos = idx >> 5;
    float inv = powf(10000.0f, -(float)(2 * j) / 64.0f);
    float th = (float)pos * inv;
    g_rope[idx] = cosf(th);
    g_rope[NF_MAX * 32 + idx] = sinf(th);
}

// ---------------------------------------------------------------------------
// tf32 mma.sync GEMM (unchanged from round 3): C = A @ Bt^T + bias
// ---------------------------------------------------------------------------
__device__ __forceinline__ void load_tile(const float* Ag, const float* Bg, int K,
                                          uint32_t aBuf, uint32_t bBuf, int tid)
{
#pragma unroll
    for (int j = 0; j < 4; j++) {
        int idx = j * 256 + tid;
        int row = idx >> 3, k4 = idx & 7;
        uint32_t off = sw128((uint32_t)(row * 128 + k4 * 16));
        CP_A16(aBuf + off, Ag + (size_t)row * K + k4 * 4);
        CP_A16(bBuf + off, Bg + (size_t)row * K + k4 * 4);
    }
}

__global__ __launch_bounds__(256)
void gemm_tf32(const float* __restrict__ A, const float* __restrict__ Bt,
               const float* __restrict__ bias, float* __restrict__ C,
               int M, int N, int K)
{
    extern __shared__ char smraw[];
    uint32_t base = smem_u32(smraw);
    uint32_t data = (base + 1023u) & ~1023u;

    int tid = threadIdx.x, lane = tid & 31, wid = tid >> 5;
    int wm = (wid >> 2) * 64;
    int wn = (wid & 3) * 32;

    const float* Ag = A  + (size_t)blockIdx.y * 128 * K;
    const float* Bg = Bt + (size_t)blockIdx.x * 128 * K;

    float acc[4][4][4];
#pragma unroll
    for (int i = 0; i < 4; i++)
#pragma unroll
        for (int j = 0; j < 4; j++)
#pragma unroll
            for (int k = 0; k < 4; k++) acc[i][j][k] = 0.f;

    int T = K >> 5;
    load_tile(Ag, Bg, K, data, data + 16384u, tid);
    CP_COMMIT();

    int lmat = lane >> 3, lrow = lane & 7;
    int frow = ((lmat & 2) ? 8 : 0) + lrow;
    int fcol = (lmat & 1) * 16;

    for (int t = 0; t < T; ++t) {
        int st = t & 1;
        if (t + 1 < T) {
            uint32_t nb = data + (uint32_t)((t + 1) & 1) * 32768u;
            load_tile(Ag + (t + 1) * 32, Bg + (t + 1) * 32, K, nb, nb + 16384u, tid);
            CP_COMMIT();
            CP_WAIT1();
        } else {
            CP_WAIT0();
        }
        __syncthreads();

        uint32_t aB = data + (uint32_t)st * 32768u;
        uint32_t bB = aB + 16384u;
#pragma unroll
        for (int kk = 0; kk < 4; ++kk) {
            uint32_t af[4][4], bf[2][4];
#pragma unroll
            for (int mi = 0; mi < 4; ++mi) {
                uint32_t addr = aB + sw128((uint32_t)((wm + mi * 16 + frow) * 128 + kk * 32 + fcol));
                LDSM4(af[mi], addr);
            }
#pragma unroll
            for (int nj = 0; nj < 2; ++nj) {
                uint32_t addr = bB + sw128((uint32_t)((wn + nj * 16 + frow) * 128 + kk * 32 + fcol));
                LDSM4(bf[nj], addr);
            }
#pragma unroll
            for (int mi = 0; mi < 4; ++mi)
#pragma unroll
                for (int ni = 0; ni < 4; ++ni) {
                    int nj = ni >> 1, lh = (ni & 1) * 2;
                    MMA_TF32(acc[mi][ni],
                             af[mi][0], af[mi][2], af[mi][1], af[mi][3],
                             bf[nj][lh], bf[nj][lh + 1]);
                }
        }
        __syncthreads();
    }

    int rbase = blockIdx.y * 128 + wm + (lane >> 2);
    int cbase = blockIdx.x * 128 + wn + (lane & 3) * 2;
#pragma unroll
    for (int mi = 0; mi < 4; ++mi) {
#pragma unroll
        for (int ni = 0; ni < 4; ++ni) {
            int c = cbase + ni * 8;
            float2 bv = *(const float2*)(bias + c);
            int r0 = rbase + mi * 16;
            float2 v0 = { acc[mi][ni][0] + bv.x, acc[mi][ni][1] + bv.y };
            *(float2*)(C + (size_t)r0 * N + c) = v0;
            float2 v1 = { acc[mi][ni][2] + bv.x, acc[mi][ni][3] + bv.y };
            *(float2*)(C + (size_t)(r0 + 8) * N + c) = v1;
        }
    }
}

// ---------------------------------------------------------------------------
// MMA flash attention with fused RoPE. grid (LQ/128, H, B), 256 threads.
// SMEM layout (byte offsets, all 128B-row swizzled subtiles):
//   QS 0       : 2 x [128][32]f  (32KB)   Q tile, scaled+rope+tf32
//   KS 32768   : 2 x [256][32]f  (64KB)   K tile, rope+tf32
//   VT 98304   : 8 x [64][32]f   (64KB)   V^T (d-major), tf32
//   PS 163840  : 4 x [128][32]f  (64KB)   P scratch for current 128-kv chunk
// ---------------------------------------------------------------------------
#define QS_OFF 0u
#define KS_OFF 32768u
#define VT_OFF 98304u
#define PS_OFF 163840u
#define ATTN_SMEM 229376

__global__ __launch_bounds__(256, 1)
void attn_kernel(const float* __restrict__ Q, const float* __restrict__ Kg,
                 const float* __restrict__ Vg, float* __restrict__ O,
                 const int* __restrict__ nf_ptr)
{
    extern __shared__ char sm[];
    uint32_t smb = smem_u32(sm);

    int tid = threadIdx.x, l = tid & 31, w = tid >> 5;
    int b = blockIdx.z, h = blockIdx.y, qt = blockIdx.x;
    int kvh = h >> 2;                      // H/KVH = 4
    int nf = *nf_ptr;
    bool rope = (nf > 1) && (nf <= NF_MAX);
    int qdiv = rope ? (LQ_ / nf) : 1;
    int kdiv = rope ? (LKV_ / nf) : 1;

    // ---- load Q tile (rope + scale + tf32) : 1 unit/thread -----------------
    {
        int row = tid >> 1, part = tid & 1;
        int qglob = qt * 128 + row;
        const float* src = Q + ((size_t)(b * LQ_ + qglob)) * D_ + h * HD_;
        int pos = rope ? (qglob / qdiv) : 0;
        const float* ct = g_rope + pos * 32;
        const float* st = g_rope + NF_MAX * 32 + pos * 32;
#pragma unroll
        for (int jj = 0; jj < 4; jj++) {
            int j = part * 16 + jj * 4;
            float4 x1 = *(const float4*)(src + j);
            float4 x2 = *(const float4*)(src + j + 32);
            float y1[4], y2[4];
            float a1[4] = {x1.x, x1.y, x1.z, x1.w};
            float a2[4] = {x2.x, x2.y, x2.z, x2.w};
#pragma unroll
            for (int e = 0; e < 4; e++) {
                float c = 1.f, s = 0.f;
                if (rope) { c = ct[j + e]; s = st[j + e]; }
                y1[e] = to_tf32((a1[e] * c - a2[e] * s) * 0.125f);
                y2[e] = to_tf32((a2[e] * c + a1[e] * s) * 0.125f);
            }
            uint32_t o0 = QS_OFF + sw128((uint32_t)(row * 128 + j * 4));
            uint32_t o1 = QS_OFF + 16384u + sw128((uint32_t)(row * 128 + j * 4));
            *(float4*)(sm + o0) = make_float4(y1[0], y1[1], y1[2], y1[3]);
            *(float4*)(sm + o1) = make_float4(y2[0], y2[1], y2[2], y2[3]);
        }
    }

    // ---- load K tile (rope + tf32) : 2 units/thread ------------------------
#pragma unroll
    for (int u = tid; u < 512; u += 256) {
        int row = u >> 1, part = u & 1;
        const float* src = Kg + ((size_t)(b * LKV_ + row) * KVH_ + kvh) * HD_;
        int pos = rope ? (row / kdiv) : 0;
        const float* ct = g_rope + pos * 32;
        const float* st = g_rope + NF_MAX * 32 + pos * 32;
#pragma unroll
        for (int jj = 0; jj < 4; jj++) {
            int j = part * 16 + jj * 4;
            float4 x1 = *(const float4*)(src + j);
            float4 x2 = *(const float4*)(src + j + 32);
            float a1[4] = {x1.x, x1.y, x1.z, x1.w};
            float a2[4] = {x2.x, x2.y, x2.z, x2.w};
            float y1[4], y2[4];
#pragma unroll
            for (int e = 0; e < 4; e++) {
                float c = 1.f, s = 0.f;
                if (rope) { c = ct[j + e]; s = st[j + e]; }
                y1[e] = to_tf32(a1[e] * c - a2[e] * s);
                y2[e] = to_tf32(a2[e] * c + a1[e] * s);
            }
            uint32_t o0 = KS_OFF + sw128((uint32_t)(row * 128 + j * 4));
            uint32_t o1 = KS_OFF + 32768u + sw128((uint32_t)(row * 128 + j * 4));
            *(float4*)(sm + o0) = make_float4(y1[0], y1[1], y1[2], y1[3]);
            *(float4*)(sm + o1) = make_float4(y2[0], y2[1], y2[2], y2[3]);
        }
    }

    // ---- load V transposed (tf32) ------------------------------------------
#pragma unroll
    for (int i = 0; i < 16; i++) {
        int kv = w * 32 + (l & 15) + ((i & 1) << 4);
        int d4 = (l >> 4) + ((i >> 1) << 1);       // 0..15
        const float* src = Vg + ((size_t)(b * LKV_ + kv) * KVH_ + kvh) * HD_ + d4 * 4;
        float4 v = *(const float4*)src;
        float a[4] = {to_tf32(v.x), to_tf32(v.y), to_tf32(v.z), to_tf32(v.w)};
        uint32_t base = VT_OFF + (uint32_t)(kv >> 5) * 8192u;
#pragma unroll
        for (int c = 0; c < 4; c++) {
            int d = 4 * d4 + c;
            *(float*)(sm + base + sw128((uint32_t)(d * 128 + (kv & 31) * 4))) = a[c];
        }
    }
    __syncthreads();

    // ---- compute (per-warp independent) ------------------------------------
    int lmat = l >> 3, lrow = l & 7;
    int frow = ((lmat & 2) ? 8 : 0) + lrow;
    int fcol = (lmat & 1) * 16;
    int mrow = w * 16 + frow;

    uint32_t qf[8][4];
#pragma unroll
    for (int kk = 0; kk < 8; kk++) {
        uint32_t a = smb + QS_OFF + (uint32_t)(kk >> 2) * 16384u
                   + sw128((uint32_t)(mrow * 128 + (kk & 3) * 32 + fcol));
        LDSM4(qf[kk], a);
    }

    float oacc[8][4];
#pragma unroll
    for (int i = 0; i < 8; i++)
#pragma unroll
        for (int j = 0; j < 4; j++) oacc[i][j] = 0.f;
    float rs0 = 0.f, rs1 = 0.f;

#pragma unroll
    for (int c = 0; c < 2; c++) {
        float sc[16][4];
#pragma unroll
        for (int i = 0; i < 16; i++)
#pragma unroll
            for (int j = 0; j < 4; j++) sc[i][j] = 0.f;

        // S = Q @ K^T for kv chunk [c*128, c*128+128)
#pragma unroll
        for (int ng = 0; ng < 8; ng++) {
            int kvrow = c * 128 + ng * 16 + frow;
#pragma unroll
            for (int kk = 0; kk < 8; kk++) {
                uint32_t bf[4];
                uint32_t a = smb + KS_OFF + (uint32_t)(kk >> 2) * 32768u
                           + sw128((uint32_t)(kvrow * 128 + (kk & 3) * 32 + fcol));
                LDSM4(bf, a);
                MMA_TF32(sc[2 * ng],     qf[kk][0], qf[kk][2], qf[kk][1], qf[kk][3], bf[0], bf[1]);
                MMA_TF32(sc[2 * ng + 1], qf[kk][0], qf[kk][2], qf[kk][1], qf[kk][3], bf[2], bf[3]);
            }
        }

        // softmax (no max-sub; scores ~N(0,1)) + store P to SMEM
        int r0 = w * 16 + (l >> 2);
#pragma unroll
        for (int nt = 0; nt < 16; nt++) {
            float p0 = __expf(sc[nt][0]);
            float p1 = __expf(sc[nt][1]);
            float p2 = __expf(sc[nt][2]);
            float p3 = __expf(sc[nt][3]);
            rs0 += p0 + p1;
            rs1 += p2 + p3;
            int kvl = nt * 8 + 2 * (l & 3);
            uint32_t bo = PS_OFF + (uint32_t)(kvl >> 5) * 16384u;
            *(float2*)(sm + bo + sw128((uint32_t)(r0 * 128 + (kvl & 31) * 4)))
                = make_float2(to_tf32(p0), to_tf32(p1));
            *(float2*)(sm + bo + sw128((uint32_t)((r0 + 8) * 128 + (kvl & 31) * 4)))
                = make_float2(to_tf32(p2), to_tf32(p3));
        }
        __syncwarp();

        // O += P @ V
        uint32_t pf[16][4];
#pragma unroll
        for (int kt = 0; kt < 16; kt++) {
            uint32_t a = smb + PS_OFF + (uint32_t)(kt >> 2) * 16384u
                       + sw128((uint32_t)(mrow * 128 + (kt & 3) * 32 + fcol));
            LDSM4(pf[kt], a);
        }
#pragma unroll
        for (int dg = 0; dg < 4; dg++) {
#pragma unroll
            for (int kt = 0; kt < 16; kt++) {
                uint32_t bf[4];
                uint32_t a = smb + VT_OFF + (uint32_t)(c * 4 + (kt >> 2)) * 8192u
                           + sw128((uint32_t)((dg * 16 + frow) * 128 + (kt & 3) * 32 + fcol));
                LDSM4(bf, a);
                MMA_TF32(oacc[2 * dg],     pf[kt][0], pf[kt][2], pf[kt][1], pf[kt][3], bf[0], bf[1]);
                MMA_TF32(oacc[2 * dg + 1], pf[kt][0], pf[kt][2], pf[kt][1], pf[kt][3], bf[2], bf[3]);
            }
        }
        __syncwarp();   // protect PS before next chunk overwrites
    }

    // ---- normalize + store --------------------------------------------------
    rs0 += __shfl_xor_sync(0xFFFFFFFFu, rs0, 1);
    rs0 += __shfl_xor_sync(0xFFFFFFFFu, rs0, 2);
    rs1 += __shfl_xor_sync(0xFFFFFFFFu, rs1, 1);
    rs1 += __shfl_xor_sync(0xFFFFFFFFu, rs1, 2);
    float inv0 = 1.0f / rs0, inv1 = 1.0f / rs1;

    int q0 = qt * 128 + w * 16 + (l >> 2);
    float* o0 = O + ((size_t)(b * LQ_ + q0)) * D_ + h * HD_;
    float* o1 = o0 + 8 * D_;
#pragma unroll
    for (int nt = 0; nt < 8; nt++) {
        int dcol = nt * 8 + 2 * (l & 3);
        *(float2*)(o0 + dcol) = make_float2(to_tf32(oacc[nt][0] * inv0),
                                            to_tf32(oacc[nt][1] * inv0));
        *(float2*)(o1 + dcol) = make_float2(to_tf32(oacc[nt][2] * inv1),
                                            to_tf32(oacc[nt][3] * inv1));
    }
}

// ---------------------------------------------------------------------------
extern "C" void kernel_launch(void* const* d_in, const int* in_sizes, int n_in,
                              void* d_out, int out_size)
{
    const float* patches = (const float*)d_in[0];
    const float* latents = (const float*)d_in[1];
    const float* Wq = (const float*)d_in[2];
    const float* bq = (const float*)d_in[3];
    const float* Wk = (const float*)d_in[4];
    const float* bk = (const float*)d_in[5];
    const float* Wv = (const float*)d_in[6];
    const float* bv = (const float*)d_in[7];
    const float* Wo = (const float*)d_in[8];
    const float* bo = (const float*)d_in[9];
    const int*   nf = (const int*)d_in[10];
    float* out = (float*)d_out;

    float *Pd, *Ld, *Qd, *Kd, *Vd, *Ad, *WtQ, *WtK, *WtV, *WtO;
    cudaGetSymbolAddress((void**)&Pd,  g_P);
    cudaGetSymbolAddress((void**)&Ld,  g_L);
    cudaGetSymbolAddress((void**)&Qd,  g_Q);
    cudaGetSymbolAddress((void**)&Kd,  g_K);
    cudaGetSymbolAddress((void**)&Vd,  g_V);
    cudaGetSymbolAddress((void**)&Ad,  g_attn);
    cudaGetSymbolAddress((void**)&WtQ, g_WtQ);
    cudaGetSymbolAddress((void**)&WtK, g_WtK);
    cudaGetSymbolAddress((void**)&WtV, g_WtV);
    cudaGetSymbolAddress((void**)&WtO, g_WtO);

    const int GEMM_SMEM = 1024 + 4 * 16384;
    cudaFuncSetAttribute(gemm_tf32, cudaFuncAttributeMaxDynamicSharedMemorySize, GEMM_SMEM);
    cudaFuncSetAttribute(attn_kernel, cudaFuncAttributeMaxDynamicSharedMemorySize, ATTN_SMEM);

    // 0) prep
    dim3 tb(32, 8);
    transpose_kernel<<<dim3(D_ / 32, D_ / 32), tb>>>(Wq, WtQ, D_, D_);
    transpose_kernel<<<dim3((KVH_ * HD_) / 32, D_ / 32), tb>>>(Wk, WtK, D_, KVH_ * HD_);
    transpose_kernel<<<dim3((KVH_ * HD_) / 32, D_ / 32), tb>>>(Wv, WtV, D_, KVH_ * HD_);
    transpose_kernel<<<dim3(D_ / 32, D_ / 32), tb>>>(Wo, WtO, D_, D_);
    rope_table_kernel<<<(NF_MAX * 32) / 256, 256>>>(nf);
    int np4 = B_ * LQ_ * D_ / 4;
    cvt_tf32_kernel<<<(np4 + 255) / 256, 256>>>(patches, Pd, np4);
    int nl4 = B_ * LKV_ * D_ / 4;
    cvt_tf32_kernel<<<(nl4 + 255) / 256, 256>>>(latents, Ld, nl4);

    // 1) Q projection
    gemm_tf32<<<dim3(D_ / 128, (B_ * LQ_) / 128), 256, GEMM_SMEM>>>(
        Pd, WtQ, bq, Qd, B_ * LQ_, D_, D_);

    // 2) K / V projections
    gemm_tf32<<<dim3((KVH_ * HD_) / 128, (B_ * LKV_) / 128), 256, GEMM_SMEM>>>(
        Ld, WtK, bk, Kd, B_ * LKV_, KVH_ * HD_, D_);
    gemm_tf32<<<dim3((KVH_ * HD_) / 128, (B_ * LKV_) / 128), 256, GEMM_SMEM>>>(
        Ld, WtV, bv, Vd, B_ * LKV_, KVH_ * HD_, D_);

    // 3) attention (mma + fused RoPE) -> tf32-rounded g_attn
    dim3 ga(LQ_ / 128, H_, B_);
    attn_kernel<<<ga, 256, ATTN_SMEM>>>(Qd, Kd, Vd, Ad, nf);

    // 4) output projection
    gemm_tf32<<<dim3(D_ / 128, (B_ * LQ_) / 128), 256, GEMM_SMEM>>>(
        Ad, WtO, bo, out, B_ * LQ_, D_, D_);
}